// round 14
// baseline (speedup 1.0000x reference)
#include <cuda_runtime.h>
#include <math.h>

#define N_RAYS   32768
#define S_USED   115        // only samples 0..114 contribute
#define GD       128
#define NCH      27

// global load (non-coherent) with 256B L2 prefetch hint: the next z-cell for
// this lane lives ~108B away, so the hint pre-stages the next reload's line.
__device__ __forceinline__ float ldg_pf(const float* p) {
    float v;
    asm("ld.global.nc.L2::256B.f32 %0, [%1];" : "=f"(v) : "l"(p));
    return v;
}

// march loop body; DO_CLAMP is a compile-time 0/1 literal.
// z-lerp differences (e10..e76) hoisted to the reload path.
#define MARCH_LOOP(DO_CLAMP)                                                  \
    {                                                                         \
        float v0=0.f,v2=0.f,v4=0.f,v6=0.f;                                    \
        float e10=0.f,e32=0.f,e54=0.f,e76=0.f;                                \
        float Bprev = -1.f;                                                   \
        _Pragma("unroll 2")                                                   \
        for (int s = sbeg; s < send; s++) {                                   \
            float cx = px, cy = py, cz = pz;                                  \
            if (DO_CLAMP) {                                                   \
                cx = fminf(fmaxf(cx, 0.f), 126.9999f);                        \
                cy = fminf(fmaxf(cy, 0.f), 126.9999f);                        \
                cz = fminf(fmaxf(cz, 0.f), 126.9999f);                        \
            }                                                                 \
            float fx0 = floorf(cx), fy0 = floorf(cy), fz0 = floorf(cz);       \
            float fx = cx - fx0, fy = cy - fy0, fz = cz - fz0;                \
            float B = fmaf(fy0, 128.f, fmaf(fx0, 16384.f, fz0));              \
            if (B != Bprev) {                                                 \
                int b = (int)B * stride;                                      \
                const float* cell  = bptr + b;                                \
                const float* cellx = cell + (s128 << 7);                      \
                v0 = ldg_pf(cell);                                            \
                float v1 = ldg_pf(cell + s1);                                 \
                v2 = ldg_pf(cell + s128);                                     \
                float v3 = ldg_pf(cell + s128 + s1);                          \
                v4 = ldg_pf(cellx);                                           \
                float v5 = ldg_pf(cellx + s1);                                \
                v6 = ldg_pf(cellx + s128);                                    \
                float v7 = ldg_pf(cellx + s128 + s1);                         \
                e10 = v1 - v0;  e32 = v3 - v2;                                \
                e54 = v5 - v4;  e76 = v7 - v6;                                \
                Bprev = B;                                                    \
            }                                                                 \
            float c00 = fmaf(fz, e10, v0);                                    \
            float c01 = fmaf(fz, e32, v2);                                    \
            float c10 = fmaf(fz, e54, v4);                                    \
            float c11 = fmaf(fz, e76, v6);                                    \
            float d0  = fmaf(fy, c01 - c00, c00);                             \
            float d1  = fmaf(fy, c11 - c10, c10);                             \
            float acc = fmaf(fx, d1 - d0, d0);                                \
            if (lane < 28)                                                    \
                coef[s][lane] = acc * mysh;                                   \
            px += sx;  py += sy;  pz += sz;                                   \
        }                                                                     \
    }

__global__ __launch_bounds__(128, 12)
void rf_render_kernel(const float* __restrict__ xin,
                      const float* __restrict__ din,
                      const float* __restrict__ tminp,
                      const float* __restrict__ tmaxp,
                      const float* __restrict__ grid,
                      const float* __restrict__ opacity,
                      float* __restrict__ out)
{
    __shared__ float coef[S_USED][29];
    __shared__ float shs[9];
    __shared__ float wsum[4];
    __shared__ float red[4][3];

    const int ray  = blockIdx.x;
    const int tid  = threadIdx.x;
    const int lane = tid & 31;
    const int warp = tid >> 5;

    const float dx = din[ray*3+0];
    const float dy = din[ray*3+1];
    const float dz = din[ray*3+2];
    const float ox = xin[ray*3+0];
    const float oy = xin[ray*3+1];
    const float oz = xin[ray*3+2];
    const float t0 = tminp[ray];
    const float range = tmaxp[ray] - t0;

    if (tid < 9) {
        float v = 0.f;
        switch (tid) {
            case 0: v = 0.28209479177387814f; break;
            case 1: v = -0.4886025119029199f * dy; break;
            case 2: v =  0.4886025119029199f * dz; break;
            case 3: v = -0.4886025119029199f * dx; break;
            case 4: v =  1.0925484305920792f * dx * dy; break;
            case 5: v = -1.0925484305920792f * dy * dz; break;
            case 6: v =  0.31539156525252005f * (2.f*dz*dz - dx*dx - dy*dy); break;
            case 7: v = -1.0925484305920792f * dx * dz; break;
            case 8: v =  0.5462742152960396f * (dx*dx - dy*dy); break;
        }
        shs[tid] = v;
    }
    __syncthreads();

    const float mysh = (lane < 27) ? shs[lane % 9] : 1.f;

    // lanes 0..26 -> grid channel `lane`; lanes 27..31 -> opacity (dupes discarded)
    const float* bptr  = (lane < NCH) ? (grid + lane) : opacity;
    const int   stride = (lane < NCH) ? NCH : 1;
    const int   s1     = stride;
    const int   s128   = stride << 7;

    const int chunk = (S_USED + 3) / 4;           // 29
    const int sbeg  = warp * chunk;
    const int send  = min(sbeg + chunk, S_USED);

    const float step = range * (1.f / 128.f);
    const float tb   = fmaf(range, fmaf((float)sbeg, 1.f/128.f, 0.05f), t0);
    float px = fmaf(tb, dx, ox);
    float py = fmaf(tb, dy, oy);
    float pz = fmaf(tb, dz, oz);
    const float sx = step * dx, sy = step * dy, sz = step * dz;

    // endpoint test: positions affine in s -> chunk fully in-bounds iff both
    // endpoints are. Warp-uniform.
    {
        float n  = (float)(send - 1 - sbeg);
        float ex = fmaf(n, sx, px);
        float ey = fmaf(n, sy, py);
        float ez = fmaf(n, sz, pz);
        float mn = fminf(fminf(fminf(px, ex), fminf(py, ey)), fminf(pz, ez));
        float mx = fmaxf(fmaxf(fmaxf(px, ex), fmaxf(py, ey)), fmaxf(pz, ez));
        if (mn >= 0.f && mx <= 126.9999f) {
            MARCH_LOOP(0)
        } else {
            MARCH_LOOP(1)
        }
    }
    __syncthreads();

    // ---- phase 2: thread-per-sample dot + transmittance scan + reduce ----
    float dts = 0.f;
    float c0 = 0.f, c1 = 0.f, c2 = 0.f;
    if (tid < S_USED) {
        const float* row = coef[tid];
        #pragma unroll
        for (int j = 0; j < 9; j++) {
            c0 += row[j];
            c1 += row[9 + j];
            c2 += row[18 + j];
        }
        float op = fminf(fmaxf(row[27], 0.f), 100000.f);
        float delta = range * (1.f / 128.f);
        dts = -delta * op;
    }

    float xs = dts;
    #pragma unroll
    for (int off = 1; off < 32; off <<= 1) {
        float n = __shfl_up_sync(0xffffffffu, xs, off);
        if (lane >= off) xs += n;
    }
    if (lane == 31) wsum[warp] = xs;
    __syncthreads();
    float offacc = 0.f;
    #pragma unroll
    for (int w = 0; w < 4; w++)
        if (w < warp) offacc += wsum[w];
    float cum = offacc + xs - dts;     // exclusive prefix

    float r0 = 0.f, r1 = 0.f, r2 = 0.f;
    if (tid < S_USED) {
        float wgt = expf(cum) * (1.f - expf(dts));
        c0 = fminf(fmaxf(c0 + 0.5f, 0.f), 100000.f);
        c1 = fminf(fmaxf(c1 + 0.5f, 0.f), 100000.f);
        c2 = fminf(fmaxf(c2 + 0.5f, 0.f), 100000.f);
        r0 = wgt * c0;  r1 = wgt * c1;  r2 = wgt * c2;
    }

    #pragma unroll
    for (int off = 16; off > 0; off >>= 1) {
        r0 += __shfl_down_sync(0xffffffffu, r0, off);
        r1 += __shfl_down_sync(0xffffffffu, r1, off);
        r2 += __shfl_down_sync(0xffffffffu, r2, off);
    }
    if (lane == 0) {
        red[warp][0] = r0;  red[warp][1] = r1;  red[warp][2] = r2;
    }
    __syncthreads();
    if (tid == 0) {
        out[ray*3+0] = red[0][0] + red[1][0] + red[2][0] + red[3][0];
        out[ray*3+1] = red[0][1] + red[1][1] + red[2][1] + red[3][1];
        out[ray*3+2] = red[0][2] + red[1][2] + red[2][2] + red[3][2];
    }
}

extern "C" void kernel_launch(void* const* d_in, const int* in_sizes, int n_in,
                              void* d_out, int out_size)
{
    const float* x       = (const float*)d_in[0];
    const float* d       = (const float*)d_in[1];
    const float* tmin    = (const float*)d_in[2];
    const float* tmax    = (const float*)d_in[3];
    const float* grid    = (const float*)d_in[4];
    const float* opacity = (const float*)d_in[5];
    float* out = (float*)d_out;

    rf_render_kernel<<<N_RAYS, 128>>>(x, d, tmin, tmax, grid, opacity, out);
}

// round 15
// speedup vs baseline: 1.4912x; 1.4912x over previous
#include <cuda_runtime.h>
#include <math.h>

#define N_RAYS   32768
#define S_USED   115        // only samples 0..114 contribute
#define GD       128
#define NCH      27

// march loop body; DO_CLAMP is a compile-time 0/1 literal.
// z-lerp differences (e10..e76) are hoisted to the reload path: they only
// change when the cell changes.
#define MARCH_LOOP(DO_CLAMP)                                                  \
    {                                                                         \
        float v0=0.f,v2=0.f,v4=0.f,v6=0.f;                                    \
        float e10=0.f,e32=0.f,e54=0.f,e76=0.f;                                \
        float Bprev = -1.f;                                                   \
        _Pragma("unroll 4")                                                   \
        for (int s = sbeg; s < send; s++) {                                   \
            float cx = px, cy = py, cz = pz;                                  \
            if (DO_CLAMP) {                                                   \
                cx = fminf(fmaxf(cx, 0.f), 126.9999f);                        \
                cy = fminf(fmaxf(cy, 0.f), 126.9999f);                        \
                cz = fminf(fmaxf(cz, 0.f), 126.9999f);                        \
            }                                                                 \
            float fx0 = floorf(cx), fy0 = floorf(cy), fz0 = floorf(cz);       \
            float fx = cx - fx0, fy = cy - fy0, fz = cz - fz0;                \
            float B = fmaf(fy0, 128.f, fmaf(fx0, 16384.f, fz0));              \
            if (B != Bprev) {                                                 \
                int b = (int)B * stride;                                      \
                const float* cell  = bptr + b;                                \
                const float* cellx = cell + (s128 << 7);                      \
                v0 = __ldg(cell);                                             \
                float v1 = __ldg(cell + s1);                                  \
                v2 = __ldg(cell + s128);                                      \
                float v3 = __ldg(cell + s128 + s1);                           \
                v4 = __ldg(cellx);                                            \
                float v5 = __ldg(cellx + s1);                                 \
                v6 = __ldg(cellx + s128);                                     \
                float v7 = __ldg(cellx + s128 + s1);                          \
                e10 = v1 - v0;  e32 = v3 - v2;                                \
                e54 = v5 - v4;  e76 = v7 - v6;                                \
                Bprev = B;                                                    \
            }                                                                 \
            float c00 = fmaf(fz, e10, v0);                                    \
            float c01 = fmaf(fz, e32, v2);                                    \
            float c10 = fmaf(fz, e54, v4);                                    \
            float c11 = fmaf(fz, e76, v6);                                    \
            float d0  = fmaf(fy, c01 - c00, c00);                             \
            float d1  = fmaf(fy, c11 - c10, c10);                             \
            float acc = fmaf(fx, d1 - d0, d0);                                \
            if (lane < 28)                                                    \
                coef[s][lane] = acc * mysh;                                   \
            px += sx;  py += sy;  pz += sz;                                   \
        }                                                                     \
    }

__global__ __launch_bounds__(128, 12)
void rf_render_kernel(const float* __restrict__ xin,
                      const float* __restrict__ din,
                      const float* __restrict__ tminp,
                      const float* __restrict__ tmaxp,
                      const float* __restrict__ grid,
                      const float* __restrict__ opacity,
                      float* __restrict__ out)
{
    __shared__ float coef[S_USED][29];
    __shared__ float shs[9];
    __shared__ float wsum[4];
    __shared__ float red[4][3];

    const int ray  = blockIdx.x;
    const int tid  = threadIdx.x;
    const int lane = tid & 31;
    const int warp = tid >> 5;

    const float dx = din[ray*3+0];
    const float dy = din[ray*3+1];
    const float dz = din[ray*3+2];
    const float ox = xin[ray*3+0];
    const float oy = xin[ray*3+1];
    const float oz = xin[ray*3+2];
    const float t0 = tminp[ray];
    const float range = tmaxp[ray] - t0;

    if (tid < 9) {
        float v = 0.f;
        switch (tid) {
            case 0: v = 0.28209479177387814f; break;
            case 1: v = -0.4886025119029199f * dy; break;
            case 2: v =  0.4886025119029199f * dz; break;
            case 3: v = -0.4886025119029199f * dx; break;
            case 4: v =  1.0925484305920792f * dx * dy; break;
            case 5: v = -1.0925484305920792f * dy * dz; break;
            case 6: v =  0.31539156525252005f * (2.f*dz*dz - dx*dx - dy*dy); break;
            case 7: v = -1.0925484305920792f * dx * dz; break;
            case 8: v =  0.5462742152960396f * (dx*dx - dy*dy); break;
        }
        shs[tid] = v;
    }
    __syncthreads();

    const float mysh = (lane < 27) ? shs[lane % 9] : 1.f;

    // lanes 0..26 -> grid channel `lane`; lanes 27..31 -> opacity (dupes discarded)
    const float* bptr  = (lane < NCH) ? (grid + lane) : opacity;
    const int   stride = (lane < NCH) ? NCH : 1;
    const int   s1     = stride;
    const int   s128   = stride << 7;

    const int chunk = (S_USED + 3) / 4;           // 29
    const int sbeg  = warp * chunk;
    const int send  = min(sbeg + chunk, S_USED);

    const float step = range * (1.f / 128.f);
    const float tb   = fmaf(range, fmaf((float)sbeg, 1.f/128.f, 0.05f), t0);
    float px = fmaf(tb, dx, ox);
    float py = fmaf(tb, dy, oy);
    float pz = fmaf(tb, dz, oz);
    const float sx = step * dx, sy = step * dy, sz = step * dz;

    // endpoint test: positions affine in s -> chunk fully in-bounds iff both
    // endpoints are. Warp-uniform.
    {
        float n  = (float)(send - 1 - sbeg);
        float ex = fmaf(n, sx, px);
        float ey = fmaf(n, sy, py);
        float ez = fmaf(n, sz, pz);
        float mn = fminf(fminf(fminf(px, ex), fminf(py, ey)), fminf(pz, ez));
        float mx = fmaxf(fmaxf(fmaxf(px, ex), fmaxf(py, ey)), fmaxf(pz, ez));
        if (mn >= 0.f && mx <= 126.9999f) {
            MARCH_LOOP(0)
        } else {
            MARCH_LOOP(1)
        }
    }
    __syncthreads();

    // ---- phase 2: thread-per-sample dot + transmittance scan + reduce ----
    float dts = 0.f;
    float c0 = 0.f, c1 = 0.f, c2 = 0.f;
    if (tid < S_USED) {
        const float* row = coef[tid];
        #pragma unroll
        for (int j = 0; j < 9; j++) {
            c0 += row[j];
            c1 += row[9 + j];
            c2 += row[18 + j];
        }
        float op = fminf(fmaxf(row[27], 0.f), 100000.f);
        float delta = range * (1.f / 128.f);
        dts = -delta * op;
    }

    float xs = dts;
    #pragma unroll
    for (int off = 1; off < 32; off <<= 1) {
        float n = __shfl_up_sync(0xffffffffu, xs, off);
        if (lane >= off) xs += n;
    }
    if (lane == 31) wsum[warp] = xs;
    __syncthreads();
    float offacc = 0.f;
    #pragma unroll
    for (int w = 0; w < 4; w++)
        if (w < warp) offacc += wsum[w];
    float cum = offacc + xs - dts;     // exclusive prefix

    float r0 = 0.f, r1 = 0.f, r2 = 0.f;
    if (tid < S_USED) {
        float wgt = expf(cum) * (1.f - expf(dts));
        c0 = fminf(fmaxf(c0 + 0.5f, 0.f), 100000.f);
        c1 = fminf(fmaxf(c1 + 0.5f, 0.f), 100000.f);
        c2 = fminf(fmaxf(c2 + 0.5f, 0.f), 100000.f);
        r0 = wgt * c0;  r1 = wgt * c1;  r2 = wgt * c2;
    }

    #pragma unroll
    for (int off = 16; off > 0; off >>= 1) {
        r0 += __shfl_down_sync(0xffffffffu, r0, off);
        r1 += __shfl_down_sync(0xffffffffu, r1, off);
        r2 += __shfl_down_sync(0xffffffffu, r2, off);
    }
    if (lane == 0) {
        red[warp][0] = r0;  red[warp][1] = r1;  red[warp][2] = r2;
    }
    __syncthreads();
    if (tid == 0) {
        out[ray*3+0] = red[0][0] + red[1][0] + red[2][0] + red[3][0];
        out[ray*3+1] = red[0][1] + red[1][1] + red[2][1] + red[3][1];
        out[ray*3+2] = red[0][2] + red[1][2] + red[2][2] + red[3][2];
    }
}

extern "C" void kernel_launch(void* const* d_in, const int* in_sizes, int n_in,
                              void* d_out, int out_size)
{
    const float* x       = (const float*)d_in[0];
    const float* d       = (const float*)d_in[1];
    const float* tmin    = (const float*)d_in[2];
    const float* tmax    = (const float*)d_in[3];
    const float* grid    = (const float*)d_in[4];
    const float* opacity = (const float*)d_in[5];
    float* out = (float*)d_out;

    rf_render_kernel<<<N_RAYS, 128>>>(x, d, tmin, tmax, grid, opacity, out);
}